// round 9
// baseline (speedup 1.0000x reference)
#include <cuda_runtime.h>
#include <cuda_fp16.h>
#include <cstdint>

// ════════════════════════════════════════════════════════════════════════
// out[dst] = Σ_r (Σ_{e: rel=r} w_e · feat[src_e]) @ W_r
//   Edges sorted into (dst>>7, rel) bins; payload packed {src|row<<20, w}.
//   One 512-thread CTA per 128-node dst tile: per rel, smem counting sort
//   by row, register aggregation (no atomics), fp16 A tile, single-chain
//   fp16 HMMA accumulated over rels, coalesced stores.
//   R9 = R7 structure (TM=128 per-tile economics) + R8 wins (packed payload,
//   single W chain, empty-bin skip).
// ════════════════════════════════════════════════════════════════════════

#define DIM       128
#define NUM_RELS  8
#define MAX_E     1048576
#define MAX_BINS  4096             // ceil(50000/128)*8 = 3128 fits
#define CAP       512
#define TM        128
#define ROWB      272              // padded fp16 row: 136 halves
#define CSTRIDE   132              // staged-C f32 row stride

// SMEM layout (bytes):
#define OFF_A     0                // fp16 A [128][136]     34816
#define OFF_W     34816            // fp16 W [128][136]     34816  -> 69632
#define OFF_SPK   69632            // uint2 [CAP]            4096
#define OFF_OPK   73728            // uint2 [CAP]            4096
#define OFF_HIST  77824            // int [128]               512
#define OFF_RS    78336            // int [129] (+pad)        528
#define OFF_CUR   78864            // int [128]               512
#define SMEM_F    79376
// C staging [128][132] f32 (67584 B) aliases OFF_A.. after the mainloop.

// ---- device scratch ----
__device__ int    g_binCnt[MAX_BINS];
__device__ int    g_binOff[MAX_BINS + 1];
__device__ int    g_binCur[MAX_BINS];
__device__ uint2  g_pack[MAX_E];
__device__ __half g_Wh[NUM_RELS][DIM * DIM];

// ════════════════ PTX helpers ═══════════════════════════════════════════
__device__ __forceinline__ uint32_t smem_u32(const void* p) {
    uint32_t a;
    asm("{ .reg .u64 t; cvta.to.shared.u64 t, %1; cvt.u32.u64 %0, t; }" : "=r"(a) : "l"(p));
    return a;
}
__device__ __forceinline__ void ldsm_x4(uint32_t* r, uint32_t addr) {
    asm volatile("ldmatrix.sync.aligned.m8n8.x4.shared.b16 {%0,%1,%2,%3}, [%4];"
                 : "=r"(r[0]), "=r"(r[1]), "=r"(r[2]), "=r"(r[3]) : "r"(addr));
}
__device__ __forceinline__ void ldsm_x4_t(uint32_t* r, uint32_t addr) {
    asm volatile("ldmatrix.sync.aligned.m8n8.x4.trans.shared.b16 {%0,%1,%2,%3}, [%4];"
                 : "=r"(r[0]), "=r"(r[1]), "=r"(r[2]), "=r"(r[3]) : "r"(addr));
}
__device__ __forceinline__ void mma16816(float* d, const uint32_t* a, const uint32_t* b) {
    asm volatile("mma.sync.aligned.m16n8k16.row.col.f32.f16.f16.f32 "
                 "{%0,%1,%2,%3}, {%4,%5,%6,%7}, {%8,%9}, {%0,%1,%2,%3};"
                 : "+f"(d[0]), "+f"(d[1]), "+f"(d[2]), "+f"(d[3])
                 : "r"(a[0]), "r"(a[1]), "r"(a[2]), "r"(a[3]), "r"(b[0]), "r"(b[1]));
}

// ════════════════ prep kernels ══════════════════════════════════════════
__global__ void repack_w_kernel(const float* __restrict__ rel_emb) {
    const int r  = blockIdx.x >> 3;
    const int s0 = (blockIdx.x & 7) * 2048;
    for (int i = threadIdx.x; i < 2048; i += blockDim.x) {
        const int idx = s0 + i;
        g_Wh[r][idx] = __float2half(rel_emb[r * DIM * DIM + idx]);
    }
}

__global__ void hist_kernel(const int* __restrict__ dst, const int* __restrict__ rel, int n) {
    for (int i = blockIdx.x * blockDim.x + threadIdx.x; i < n; i += gridDim.x * blockDim.x)
        atomicAdd(&g_binCnt[(dst[i] >> 7) * NUM_RELS + rel[i]], 1);
}

__global__ void scan_kernel(int bins, int n_edges) {
    __shared__ int s_part[1024];
    const int tid  = threadIdx.x;
    const int base = tid * 4;
    int v[4], sum = 0;
    #pragma unroll
    for (int q = 0; q < 4; q++) {
        const int b = base + q;
        v[q] = (b < bins) ? g_binCnt[b] : 0;
        sum += v[q];
    }
    s_part[tid] = sum;
    __syncthreads();
    for (int off = 1; off < 1024; off <<= 1) {
        int x = 0;
        if (tid >= off) x = s_part[tid - off];
        __syncthreads();
        s_part[tid] += x;
        __syncthreads();
    }
    int run = s_part[tid] - sum;                 // exclusive
    #pragma unroll
    for (int q = 0; q < 4; q++) {
        const int b = base + q;
        if (b < bins) { g_binOff[b] = run; g_binCur[b] = run; run += v[q]; }
    }
    if (tid == 0) g_binOff[bins] = n_edges;
}

__global__ void scatter_pack_kernel(const float* __restrict__ ew,
                                    const int* __restrict__ src,
                                    const int* __restrict__ dst,
                                    const int* __restrict__ rel, int n)
{
    for (int i = blockIdx.x * blockDim.x + threadIdx.x; i < n; i += gridDim.x * blockDim.x) {
        const int d   = dst[i];
        const int key = (d >> 7) * NUM_RELS + rel[i];
        const int p   = atomicAdd(&g_binCur[key], 1);
        g_pack[p] = make_uint2((uint32_t)src[i] | ((uint32_t)(d & 127) << 20),
                               __float_as_uint(ew[i]));
    }
}

// ════════════════ fused aggregate + GEMM kernel ═════════════════════════
__global__ void __launch_bounds__(512, 1)
fused_kernel(const float* __restrict__ feat, float* __restrict__ out, int n_nodes)
{
    extern __shared__ char smem[];
    const uint32_t sbase = smem_u32(smem);
    const int tid  = threadIdx.x;
    const int wid  = tid >> 5;
    const int lane = tid & 31;
    const int t    = blockIdx.x;

    uint2* s_pk   = (uint2*)(smem + OFF_SPK);
    uint2* s_opk  = (uint2*)(smem + OFF_OPK);
    int*   s_hist = (int*)  (smem + OFF_HIST);
    int*   s_rs   = (int*)  (smem + OFF_RS);
    int*   s_cur  = (int*)  (smem + OFF_CUR);

    const int n_rem = min(TM, n_nodes - t * TM);

    // warp MMA tiling: 4x4 warps, each 32x32
    const int m_base = (wid >> 2) * 32;
    const int n_base = (wid & 3) * 32;

    float accC[2][4][4];
    #pragma unroll
    for (int mt = 0; mt < 2; mt++)
        #pragma unroll
        for (int nt = 0; nt < 4; nt++)
            #pragma unroll
            for (int q = 0; q < 4; q++) accC[mt][nt][q] = 0.f;

    const uint32_t a_lane = (uint32_t)((lane & 15) * ROWB + (lane >> 4) * 16);
    const uint32_t b_lane = (uint32_t)((lane & 15) * ROWB + ((lane >> 4) & 1) * 16);

    for (int r = 0; r < NUM_RELS; r++) {
        const int key = t * NUM_RELS + r;
        const int bs  = g_binOff[key];
        const int be  = g_binOff[key + 1];
        if (bs == be) continue;                  // uniform across CTA: safe

        float4 acc[8];
        #pragma unroll
        for (int q = 0; q < 8; q++) acc[q] = make_float4(0.f, 0.f, 0.f, 0.f);

        __syncthreads();   // previous rel's MMA done before smem reuse

        for (int c0 = bs; c0 < be; c0 += CAP) {
            const int c = min(CAP, be - c0);

            // stage packed edges (coalesced 8B each)
            for (int i = tid; i < c; i += 512) s_pk[i] = g_pack[c0 + i];
            if (tid < TM) s_hist[tid] = 0;
            __syncthreads();

            for (int i = tid; i < c; i += 512)
                atomicAdd(&s_hist[s_pk[i].x >> 20], 1);
            __syncthreads();

            // warp 0: exclusive scan of 128 bins (4 per lane)
            if (wid == 0) {
                const int b0 = lane * 4;
                const int v0 = s_hist[b0], v1 = s_hist[b0 + 1],
                          v2 = s_hist[b0 + 2], v3 = s_hist[b0 + 3];
                const int s = v0 + v1 + v2 + v3;
                int x = s;
                #pragma unroll
                for (int off = 1; off < 32; off <<= 1) {
                    const int y = __shfl_up_sync(0xFFFFFFFFu, x, off);
                    if (lane >= off) x += y;
                }
                const int excl = x - s;
                s_rs[b0]     = excl;            s_cur[b0]     = excl;
                s_rs[b0 + 1] = excl + v0;       s_cur[b0 + 1] = excl + v0;
                s_rs[b0 + 2] = excl + v0 + v1;  s_cur[b0 + 2] = excl + v0 + v1;
                s_rs[b0 + 3] = excl + v0 + v1 + v2;
                s_cur[b0 + 3] = s_rs[b0 + 3];
                if (lane == 31) s_rs[TM] = excl + s;
            }
            __syncthreads();

            // local scatter into row-sorted order
            for (int i = tid; i < c; i += 512) {
                const uint2 pk = s_pk[i];
                const int p = atomicAdd(&s_cur[pk.x >> 20], 1);
                s_opk[p] = pk;
            }
            __syncthreads();

            // aggregation: warp w owns rows [8w, 8w+8); lane -> 4 cols
            #pragma unroll
            for (int rr = 0; rr < 8; rr++) {
                int       j  = s_rs[8 * wid + rr];
                const int je = s_rs[8 * wid + rr + 1];
                for (; j + 1 < je; j += 2) {
                    const uint2 p0 = s_opk[j], p1 = s_opk[j + 1];
                    const int   s0 = p0.x & 0xFFFFF, s1 = p1.x & 0xFFFFF;
                    const float w0 = __uint_as_float(p0.y);
                    const float w1 = __uint_as_float(p1.y);
                    const float4 v0 = *(const float4*)(feat + (size_t)s0 * DIM + lane * 4);
                    const float4 v1 = *(const float4*)(feat + (size_t)s1 * DIM + lane * 4);
                    acc[rr].x += w0 * v0.x; acc[rr].y += w0 * v0.y;
                    acc[rr].z += w0 * v0.z; acc[rr].w += w0 * v0.w;
                    acc[rr].x += w1 * v1.x; acc[rr].y += w1 * v1.y;
                    acc[rr].z += w1 * v1.z; acc[rr].w += w1 * v1.w;
                }
                if (j < je) {
                    const uint2 p0 = s_opk[j];
                    const int   s0 = p0.x & 0xFFFFF;
                    const float w0 = __uint_as_float(p0.y);
                    const float4 v0 = *(const float4*)(feat + (size_t)s0 * DIM + lane * 4);
                    acc[rr].x += w0 * v0.x; acc[rr].y += w0 * v0.y;
                    acc[rr].z += w0 * v0.z; acc[rr].w += w0 * v0.w;
                }
            }
            __syncthreads();   // staging reused next chunk
        }

        // write A tile rows (fp16)
        #pragma unroll
        for (int rr = 0; rr < 8; rr++) {
            const int row = 8 * wid + rr;
            __half2 h0, h1;
            h0.x = __float2half(acc[rr].x); h0.y = __float2half(acc[rr].y);
            h1.x = __float2half(acc[rr].z); h1.y = __float2half(acc[rr].w);
            uint2 pk;
            pk.x = *(uint32_t*)&h0; pk.y = *(uint32_t*)&h1;
            *(uint2*)(smem + OFF_A + row * ROWB + lane * 8) = pk;
        }

        // load W_r into smem (padded rows)
        {
            const uint4* wg = (const uint4*)&g_Wh[r][0];
            #pragma unroll
            for (int i = tid; i < 2048; i += 512) {
                const int row = i >> 4, c16 = i & 15;
                *(uint4*)(smem + OFF_W + row * ROWB + c16 * 16) = wg[i];
            }
        }
        __syncthreads();

        // MMA: 8 k16-steps, single fp16 chain
        #pragma unroll
        for (int ks = 0; ks < 8; ks++) {
            uint32_t afr[2][4];
            #pragma unroll
            for (int mt = 0; mt < 2; mt++)
                ldsm_x4(afr[mt], sbase + OFF_A + (uint32_t)((m_base + mt * 16) * ROWB)
                                 + a_lane + (uint32_t)(ks * 32));
            uint32_t bfr[2][4];
            #pragma unroll
            for (int p = 0; p < 2; p++)
                ldsm_x4_t(bfr[p], sbase + OFF_W + (uint32_t)(ks * 16 * ROWB) + b_lane
                                     + (uint32_t)((n_base + p * 16) * 2));
            #pragma unroll
            for (int mt = 0; mt < 2; mt++)
                #pragma unroll
                for (int p = 0; p < 2; p++) {
                    mma16816(accC[mt][2 * p + 0], afr[mt], &bfr[p][0]);
                    mma16816(accC[mt][2 * p + 1], afr[mt], &bfr[p][2]);
                }
        }
    }
    __syncthreads();   // all MMA done; A/W regions reusable as C staging

    // stage C then coalesced guarded stores
    {
        float* Cst = (float*)smem;
        const int grp = lane >> 2;
        const int tig = lane & 3;
        #pragma unroll
        for (int mt = 0; mt < 2; mt++) {
            const int r0 = m_base + mt * 16 + grp;
            #pragma unroll
            for (int nt = 0; nt < 4; nt++) {
                const int col = n_base + nt * 8 + tig * 2;
                *(float2*)&Cst[r0 * CSTRIDE + col]       = make_float2(accC[mt][nt][0], accC[mt][nt][1]);
                *(float2*)&Cst[(r0 + 8) * CSTRIDE + col] = make_float2(accC[mt][nt][2], accC[mt][nt][3]);
            }
        }
    }
    __syncthreads();
    {
        const float* Cst = (const float*)smem;
        const int row = tid >> 2;          // 0..127
        const int seg = tid & 3;           // 32-float segment
        if (row < n_rem) {
            float4* op = (float4*)(out + (size_t)(t * TM + row) * DIM + seg * 32);
            const float* cp = &Cst[row * CSTRIDE + seg * 32];
            #pragma unroll
            for (int j = 0; j < 8; j++)
                op[j] = *(const float4*)(cp + j * 4);
        }
    }
}

// ════════════════ launch ════════════════════════════════════════════════
extern "C" void kernel_launch(void* const* d_in, const int* in_sizes, int n_in,
                              void* d_out, int out_size)
{
    const float* feat    = (const float*)d_in[0];
    const float* rel_emb = (const float*)d_in[1];
    const float* ew      = (const float*)d_in[2];
    const int*   src     = (const int*)d_in[3];
    const int*   dst     = (const int*)d_in[4];
    const int*   rel     = (const int*)d_in[5];
    float*       out     = (float*)d_out;

    const int n_edges = in_sizes[2];
    const int n_nodes = in_sizes[0] / DIM;
    const int tiles   = (n_nodes + TM - 1) / TM;
    const int bins    = tiles * NUM_RELS;

    static void* binCnt_ptr = nullptr;
    static int attr_set = 0;
    if (!attr_set) {
        cudaGetSymbolAddress(&binCnt_ptr, g_binCnt);
        cudaFuncSetAttribute(fused_kernel,
                             cudaFuncAttributeMaxDynamicSharedMemorySize, SMEM_F);
        attr_set = 1;
    }

    cudaMemsetAsync(binCnt_ptr, 0, (size_t)bins * sizeof(int), 0);
    repack_w_kernel<<<64, 256>>>(rel_emb);
    hist_kernel<<<1024, 256>>>(dst, rel, n_edges);
    scan_kernel<<<1, 1024>>>(bins, n_edges);
    scatter_pack_kernel<<<1024, 256>>>(ew, src, dst, rel, n_edges);
    fused_kernel<<<tiles, 512, SMEM_F>>>(feat, out, n_nodes);
}

// round 10
// speedup vs baseline: 1.3505x; 1.3505x over previous
#include <cuda_runtime.h>
#include <cuda_fp16.h>
#include <cstdint>

// ════════════════════════════════════════════════════════════════════════
// out[dst] = Σ_r (Σ_{e: rel=r} w_e · feat[src_e]) @ W_r  — fused design:
//   sort edges by (dst_tile, rel)  →  one CTA per dst tile:
//     per rel: smem-local sort by dst&127, register aggregation (no atomics),
//              A tile fp16, single-chain fp16 HMMA accumulated over rels,
//              plain coalesced stores.  No H buffer, no global atomics.
//   R10 = EXACT R7 (269.6us artifact) minus the Wlo chain — one-variable
//   controlled experiment (R8/R9 combined changes and regressed).
// ════════════════════════════════════════════════════════════════════════

#define DIM       128
#define NUM_RELS  8
#define MAX_E     1048576
#define MAX_TILES 512
#define MAX_BINS  (MAX_TILES * NUM_RELS)
#define CAP       512              // staged edges per chunk
#define ROWB      272              // padded fp16 row: 136 halves
#define CSTRIDE   132              // staged-C f32 row stride

// SMEM layout (bytes):
#define OFF_A     0                // fp16 A [128][136]     34816
#define OFF_W     34816            // fp16 W [128][136]     34816 -> 69632
#define OFF_SSRC  69632            // int  [CAP]             2048
#define OFF_SW    71680            // f32  [CAP]             2048
#define OFF_SDL   73728            // int  [CAP]             2048
#define OFF_OSRC  75776            // int  [CAP]             2048
#define OFF_OW    77824            // f32  [CAP]             2048
#define OFF_HIST  79872            // int  [128]              512
#define OFF_RS    80384            // int  [129]              528 (padded)
#define OFF_CUR   80912            // int  [128]              512
#define SMEM_F    81424
// C staging [128][132] f32 (67584 B) aliases OFF_A.. after the mainloop.

// ---- device scratch ----
__device__ int    g_binCnt[MAX_BINS];
__device__ int    g_binOff[MAX_BINS + 1];
__device__ int    g_binCur[MAX_BINS];
__device__ int    g_eidx[MAX_E];
__device__ __half g_Wh[NUM_RELS][DIM * DIM];

// ════════════════ PTX helpers ═══════════════════════════════════════════
__device__ __forceinline__ uint32_t smem_u32(const void* p) {
    uint32_t a;
    asm("{ .reg .u64 t; cvta.to.shared.u64 t, %1; cvt.u32.u64 %0, t; }" : "=r"(a) : "l"(p));
    return a;
}
__device__ __forceinline__ void ldsm_x4(uint32_t* r, uint32_t addr) {
    asm volatile("ldmatrix.sync.aligned.m8n8.x4.shared.b16 {%0,%1,%2,%3}, [%4];"
                 : "=r"(r[0]), "=r"(r[1]), "=r"(r[2]), "=r"(r[3]) : "r"(addr));
}
__device__ __forceinline__ void ldsm_x4_t(uint32_t* r, uint32_t addr) {
    asm volatile("ldmatrix.sync.aligned.m8n8.x4.trans.shared.b16 {%0,%1,%2,%3}, [%4];"
                 : "=r"(r[0]), "=r"(r[1]), "=r"(r[2]), "=r"(r[3]) : "r"(addr));
}
__device__ __forceinline__ void mma16816(float* d, const uint32_t* a, const uint32_t* b) {
    asm volatile("mma.sync.aligned.m16n8k16.row.col.f32.f16.f16.f32 "
                 "{%0,%1,%2,%3}, {%4,%5,%6,%7}, {%8,%9}, {%0,%1,%2,%3};"
                 : "+f"(d[0]), "+f"(d[1]), "+f"(d[2]), "+f"(d[3])
                 : "r"(a[0]), "r"(a[1]), "r"(a[2]), "r"(a[3]), "r"(b[0]), "r"(b[1]));
}

// ════════════════ prep kernels ══════════════════════════════════════════
__global__ void repack_w_kernel(const float* __restrict__ rel_emb) {
    const int r  = blockIdx.x >> 3;
    const int s0 = (blockIdx.x & 7) * 2048;
    for (int i = threadIdx.x; i < 2048; i += blockDim.x) {
        const int idx = s0 + i;
        g_Wh[r][idx] = __float2half(rel_emb[r * DIM * DIM + idx]);
    }
}

__global__ void hist_kernel(const int* __restrict__ dst, const int* __restrict__ rel, int n) {
    for (int i = blockIdx.x * blockDim.x + threadIdx.x; i < n; i += gridDim.x * blockDim.x)
        atomicAdd(&g_binCnt[(dst[i] >> 7) * NUM_RELS + rel[i]], 1);
}

__global__ void scan_kernel(int bins, int n_edges) {
    __shared__ int s_part[1024];
    const int tid = threadIdx.x;
    const int base = tid * 4;
    int v[4], sum = 0;
    #pragma unroll
    for (int q = 0; q < 4; q++) {
        const int b = base + q;
        v[q] = (b < bins) ? g_binCnt[b] : 0;
        sum += v[q];
    }
    s_part[tid] = sum;
    __syncthreads();
    for (int off = 1; off < 1024; off <<= 1) {
        int x = 0;
        if (tid >= off) x = s_part[tid - off];
        __syncthreads();
        s_part[tid] += x;
        __syncthreads();
    }
    int run = s_part[tid] - sum;                 // exclusive
    #pragma unroll
    for (int q = 0; q < 4; q++) {
        const int b = base + q;
        if (b < bins) { g_binOff[b] = run; g_binCur[b] = run; run += v[q]; }
    }
    if (tid == 0) g_binOff[bins] = n_edges;
}

__global__ void scatter_kernel(const int* __restrict__ dst, const int* __restrict__ rel, int n) {
    for (int i = blockIdx.x * blockDim.x + threadIdx.x; i < n; i += gridDim.x * blockDim.x) {
        const int key = (dst[i] >> 7) * NUM_RELS + rel[i];
        const int p = atomicAdd(&g_binCur[key], 1);
        g_eidx[p] = i;
    }
}

// ════════════════ fused aggregate + GEMM kernel ═════════════════════════
__global__ void __launch_bounds__(512, 1)
fused_kernel(const float* __restrict__ feat,
             const float* __restrict__ ew,
             const int*   __restrict__ src,
             const int*   __restrict__ dst,
             float*       __restrict__ out,
             int n_nodes)
{
    extern __shared__ char smem[];
    const uint32_t sbase = smem_u32(smem);
    const int tid  = threadIdx.x;
    const int wid  = tid >> 5;
    const int lane = tid & 31;
    const int t    = blockIdx.x;

    int*   s_src  = (int*)  (smem + OFF_SSRC);
    float* s_wv   = (float*)(smem + OFF_SW);
    int*   s_dl   = (int*)  (smem + OFF_SDL);
    int*   s_osrc = (int*)  (smem + OFF_OSRC);
    float* s_ow   = (float*)(smem + OFF_OW);
    int*   s_hist = (int*)  (smem + OFF_HIST);
    int*   s_rs   = (int*)  (smem + OFF_RS);
    int*   s_cur  = (int*)  (smem + OFF_CUR);

    const int n_rem = min(128, n_nodes - t * 128);

    // warp tiling for MMA: 4x4 warps, each 32x32
    const int m_base = (wid >> 2) * 32;
    const int n_base = (wid & 3) * 32;

    float accC[2][4][4];
    #pragma unroll
    for (int mt = 0; mt < 2; mt++)
        #pragma unroll
        for (int nt = 0; nt < 4; nt++)
            #pragma unroll
            for (int q = 0; q < 4; q++) accC[mt][nt][q] = 0.f;

    const uint32_t a_lane = (uint32_t)((lane & 15) * ROWB + (lane >> 4) * 16);
    const uint32_t b_lane = (uint32_t)((lane & 15) * ROWB + ((lane >> 4) & 1) * 16);

    for (int r = 0; r < NUM_RELS; r++) {
        const int key = t * NUM_RELS + r;
        const int bs  = g_binOff[key];
        const int be  = g_binOff[key + 1];

        // per-warp row accumulators (rows 8*wid .. 8*wid+7; lane -> 4 cols)
        float4 acc[8];
        #pragma unroll
        for (int q = 0; q < 8; q++) acc[q] = make_float4(0.f, 0.f, 0.f, 0.f);

        __syncthreads();   // also orders previous rel's MMA before staging reuse

        for (int c0 = bs; c0 < be; c0 += CAP) {
            const int c = min(CAP, be - c0);

            // stage edges
            for (int i = tid; i < c; i += 512) {
                const int e = g_eidx[c0 + i];
                s_src[i] = src[e];
                s_wv[i]  = ew[e];
                s_dl[i]  = dst[e] & 127;
            }
            if (tid < 128) s_hist[tid] = 0;
            __syncthreads();

            for (int i = tid; i < c; i += 512)
                atomicAdd(&s_hist[s_dl[i]], 1);
            __syncthreads();

            // warp 0: exclusive scan of 128 bins
            if (wid == 0) {
                const int b0 = lane * 4;
                const int v0 = s_hist[b0], v1 = s_hist[b0 + 1],
                          v2 = s_hist[b0 + 2], v3 = s_hist[b0 + 3];
                const int s = v0 + v1 + v2 + v3;
                int x = s;
                #pragma unroll
                for (int off = 1; off < 32; off <<= 1) {
                    const int y = __shfl_up_sync(0xFFFFFFFFu, x, off);
                    if (lane >= off) x += y;
                }
                const int excl = x - s;
                s_rs[b0]     = excl;            s_cur[b0]     = excl;
                s_rs[b0 + 1] = excl + v0;       s_cur[b0 + 1] = excl + v0;
                s_rs[b0 + 2] = excl + v0 + v1;  s_cur[b0 + 2] = excl + v0 + v1;
                s_rs[b0 + 3] = excl + v0 + v1 + v2;
                s_cur[b0 + 3] = s_rs[b0 + 3];
                if (lane == 31) s_rs[128] = excl + s;
            }
            __syncthreads();

            // scatter into dst-ordered arrays
            for (int i = tid; i < c; i += 512) {
                const int p = atomicAdd(&s_cur[s_dl[i]], 1);
                s_osrc[p] = s_src[i];
                s_ow[p]   = s_wv[i];
            }
            __syncthreads();

            // aggregation: warp w owns rows [8w, 8w+8)
            #pragma unroll
            for (int rr = 0; rr < 8; rr++) {
                int       j  = s_rs[8 * wid + rr];
                const int je = s_rs[8 * wid + rr + 1];
                for (; j + 1 < je; j += 2) {
                    const int   si0 = s_osrc[j],     si1 = s_osrc[j + 1];
                    const float w0  = s_ow[j],       w1  = s_ow[j + 1];
                    const float4 v0 = *(const float4*)(feat + (size_t)si0 * DIM + lane * 4);
                    const float4 v1 = *(const float4*)(feat + (size_t)si1 * DIM + lane * 4);
                    acc[rr].x += w0 * v0.x; acc[rr].y += w0 * v0.y;
                    acc[rr].z += w0 * v0.z; acc[rr].w += w0 * v0.w;
                    acc[rr].x += w1 * v1.x; acc[rr].y += w1 * v1.y;
                    acc[rr].z += w1 * v1.z; acc[rr].w += w1 * v1.w;
                }
                if (j < je) {
                    const int   si = s_osrc[j];
                    const float w  = s_ow[j];
                    const float4 v = *(const float4*)(feat + (size_t)si * DIM + lane * 4);
                    acc[rr].x += w * v.x; acc[rr].y += w * v.y;
                    acc[rr].z += w * v.z; acc[rr].w += w * v.w;
                }
            }
            __syncthreads();   // staging reused next chunk
        }

        // write A tile (fp16) — every row written, so no zeroing needed
        #pragma unroll
        for (int rr = 0; rr < 8; rr++) {
            const int row = 8 * wid + rr;
            __half2 h0, h1;
            h0.x = __float2half(acc[rr].x); h0.y = __float2half(acc[rr].y);
            h1.x = __float2half(acc[rr].z); h1.y = __float2half(acc[rr].w);
            uint2 pk;
            pk.x = *(uint32_t*)&h0; pk.y = *(uint32_t*)&h1;
            *(uint2*)(smem + OFF_A + row * ROWB + lane * 8) = pk;
        }

        // load W_r into smem (padded rows)
        {
            const uint4* wg = (const uint4*)&g_Wh[r][0];
            #pragma unroll
            for (int i = tid; i < 2048; i += 512) {
                const int row = i >> 4, c16 = i & 15;
                *(uint4*)(smem + OFF_W + row * ROWB + c16 * 16) = wg[i];
            }
        }
        __syncthreads();

        // MMA: 8 k16-steps, single fp16 chain
        #pragma unroll
        for (int ks = 0; ks < 8; ks++) {
            uint32_t afr[2][4];
            #pragma unroll
            for (int mt = 0; mt < 2; mt++)
                ldsm_x4(afr[mt], sbase + OFF_A + (uint32_t)((m_base + mt * 16) * ROWB)
                                 + a_lane + (uint32_t)(ks * 32));
            uint32_t bfr[2][4];
            #pragma unroll
            for (int p = 0; p < 2; p++)
                ldsm_x4_t(bfr[p], sbase + OFF_W + (uint32_t)(ks * 16 * ROWB) + b_lane
                                     + (uint32_t)((n_base + p * 16) * 2));
            #pragma unroll
            for (int mt = 0; mt < 2; mt++)
                #pragma unroll
                for (int p = 0; p < 2; p++) {
                    mma16816(accC[mt][2 * p + 0], afr[mt], &bfr[p][0]);
                    mma16816(accC[mt][2 * p + 1], afr[mt], &bfr[p][2]);
                }
        }
        // (barriers at the top of the next rel iteration order MMA vs smem reuse)
    }
    __syncthreads();   // MMA done; A/W regions reusable as C staging

    // stage C then coalesced guarded stores — no atomics
    {
        float* Cst = (float*)smem;
        const int grp = lane >> 2;
        const int tig = lane & 3;
        #pragma unroll
        for (int mt = 0; mt < 2; mt++) {
            const int r0 = m_base + mt * 16 + grp;
            #pragma unroll
            for (int nt = 0; nt < 4; nt++) {
                const int col = n_base + nt * 8 + tig * 2;
                *(float2*)&Cst[r0 * CSTRIDE + col]       = make_float2(accC[mt][nt][0], accC[mt][nt][1]);
                *(float2*)&Cst[(r0 + 8) * CSTRIDE + col] = make_float2(accC[mt][nt][2], accC[mt][nt][3]);
            }
        }
    }
    __syncthreads();
    {
        const float* Cst = (const float*)smem;
        const int row = tid >> 2;          // 0..127
        const int seg = tid & 3;           // 32-float segment
        if (row < n_rem) {
            float4* op = (float4*)(out + (size_t)(t * 128 + row) * DIM + seg * 32);
            const float* cp = &Cst[row * CSTRIDE + seg * 32];
            #pragma unroll
            for (int j = 0; j < 8; j++)
                op[j] = *(const float4*)(cp + j * 4);
        }
    }
}

// ════════════════ launch ════════════════════════════════════════════════
extern "C" void kernel_launch(void* const* d_in, const int* in_sizes, int n_in,
                              void* d_out, int out_size)
{
    const float* feat    = (const float*)d_in[0];
    const float* rel_emb = (const float*)d_in[1];
    const float* ew      = (const float*)d_in[2];
    const int*   src     = (const int*)d_in[3];
    const int*   dst     = (const int*)d_in[4];
    const int*   rel     = (const int*)d_in[5];
    float*       out     = (float*)d_out;

    const int n_edges = in_sizes[2];
    const int n_nodes = in_sizes[0] / DIM;
    const int tiles   = (n_nodes + 127) / 128;
    const int bins    = tiles * NUM_RELS;

    static void* binCnt_ptr = nullptr;
    static int attr_set = 0;
    if (!attr_set) {
        cudaGetSymbolAddress(&binCnt_ptr, g_binCnt);
        cudaFuncSetAttribute(fused_kernel,
                             cudaFuncAttributeMaxDynamicSharedMemorySize, SMEM_F);
        attr_set = 1;
    }

    cudaMemsetAsync(binCnt_ptr, 0, (size_t)bins * sizeof(int), 0);
    repack_w_kernel<<<64, 256>>>(rel_emb);
    hist_kernel<<<1024, 256>>>(dst, rel, n_edges);
    scan_kernel<<<1, 1024>>>(bins, n_edges);
    scatter_kernel<<<1024, 256>>>(dst, rel, n_edges);
    fused_kernel<<<tiles, 512, SMEM_F>>>(feat, ew, src, dst, out, n_nodes);
}

// round 11
// speedup vs baseline: 1.5907x; 1.1778x over previous
#include <cuda_runtime.h>
#include <cuda_fp16.h>
#include <cstdint>

// ════════════════════════════════════════════════════════════════════════
// out[dst] = Σ_r (Σ_{e: rel=r} w_e · feat[src_e]) @ W_r  — fused design:
//   sort edges by (dst_tile, rel) → one CTA per dst tile: per rel,
//   smem-local sort by dst&127, register aggregation, fp16 A tile,
//   single-chain fp16 HMMA accumulated over rels, coalesced stores.
//   R11 = R10 (233.6us artifact) + privatized hist/scatter (smem histograms,
//   range reservation: 800k global atomics -> ~190k) + W-load hoist.
// ════════════════════════════════════════════════════════════════════════

#define DIM       128
#define NUM_RELS  8
#define MAX_E     1048576
#define MAX_TILES 512
#define MAX_BINS  (MAX_TILES * NUM_RELS)
#define CAP       512              // staged edges per chunk
#define ROWB      272              // padded fp16 row: 136 halves
#define CSTRIDE   132              // staged-C f32 row stride
#define SORT_CTAS 64
#define BINS_CAP  4096             // >= 3128 actual bins

// SMEM layout (bytes):
#define OFF_A     0                // fp16 A [128][136]     34816
#define OFF_W     34816            // fp16 W [128][136]     34816 -> 69632
#define OFF_SSRC  69632            // int  [CAP]             2048
#define OFF_SW    71680            // f32  [CAP]             2048
#define OFF_SDL   73728            // int  [CAP]             2048
#define OFF_OSRC  75776            // int  [CAP]             2048
#define OFF_OW    77824            // f32  [CAP]             2048
#define OFF_HIST  79872            // int  [128]              512
#define OFF_RS    80384            // int  [129]              528 (padded)
#define OFF_CUR   80912            // int  [128]              512
#define SMEM_F    81424
// C staging [128][132] f32 (67584 B) aliases OFF_A.. after the mainloop.

// ---- device scratch ----
__device__ int    g_binCnt[MAX_BINS];
__device__ int    g_binOff[MAX_BINS + 1];
__device__ int    g_binCur[MAX_BINS];
__device__ int    g_eidx[MAX_E];
__device__ __half g_Wh[NUM_RELS][DIM * DIM];

// ════════════════ PTX helpers ═══════════════════════════════════════════
__device__ __forceinline__ uint32_t smem_u32(const void* p) {
    uint32_t a;
    asm("{ .reg .u64 t; cvta.to.shared.u64 t, %1; cvt.u32.u64 %0, t; }" : "=r"(a) : "l"(p));
    return a;
}
__device__ __forceinline__ void ldsm_x4(uint32_t* r, uint32_t addr) {
    asm volatile("ldmatrix.sync.aligned.m8n8.x4.shared.b16 {%0,%1,%2,%3}, [%4];"
                 : "=r"(r[0]), "=r"(r[1]), "=r"(r[2]), "=r"(r[3]) : "r"(addr));
}
__device__ __forceinline__ void ldsm_x4_t(uint32_t* r, uint32_t addr) {
    asm volatile("ldmatrix.sync.aligned.m8n8.x4.trans.shared.b16 {%0,%1,%2,%3}, [%4];"
                 : "=r"(r[0]), "=r"(r[1]), "=r"(r[2]), "=r"(r[3]) : "r"(addr));
}
__device__ __forceinline__ void mma16816(float* d, const uint32_t* a, const uint32_t* b) {
    asm volatile("mma.sync.aligned.m16n8k16.row.col.f32.f16.f16.f32 "
                 "{%0,%1,%2,%3}, {%4,%5,%6,%7}, {%8,%9}, {%0,%1,%2,%3};"
                 : "+f"(d[0]), "+f"(d[1]), "+f"(d[2]), "+f"(d[3])
                 : "r"(a[0]), "r"(a[1]), "r"(a[2]), "r"(a[3]), "r"(b[0]), "r"(b[1]));
}

// ════════════════ prep kernels ══════════════════════════════════════════
__global__ void repack_w_kernel(const float* __restrict__ rel_emb) {
    const int r  = blockIdx.x >> 3;
    const int s0 = (blockIdx.x & 7) * 2048;
    for (int i = threadIdx.x; i < 2048; i += blockDim.x) {
        const int idx = s0 + i;
        g_Wh[r][idx] = __float2half(rel_emb[r * DIM * DIM + idx]);
    }
}

// Privatized histogram: per-CTA smem hist over ALL bins, one global atomic
// per nonzero bin per CTA.
__global__ void __launch_bounds__(256)
hist_priv_kernel(const int* __restrict__ dst, const int* __restrict__ rel,
                 int n, int bins)
{
    __shared__ int s_h[BINS_CAP];
    const int tid = threadIdx.x;
    for (int i = tid; i < bins; i += 256) s_h[i] = 0;
    __syncthreads();
    const int per = (n + SORT_CTAS - 1) / SORT_CTAS;
    const int b0  = blockIdx.x * per;
    const int b1  = min(n, b0 + per);
    for (int i = b0 + tid; i < b1; i += 256)
        atomicAdd(&s_h[(dst[i] >> 7) * NUM_RELS + rel[i]], 1);
    __syncthreads();
    for (int i = tid; i < bins; i += 256) {
        const int c = s_h[i];
        if (c) atomicAdd(&g_binCnt[i], c);
    }
}

__global__ void scan_kernel(int bins, int n_edges) {
    __shared__ int s_part[1024];
    const int tid  = threadIdx.x;
    const int base = tid * 4;
    int v[4], sum = 0;
    #pragma unroll
    for (int q = 0; q < 4; q++) {
        const int b = base + q;
        v[q] = (b < bins) ? g_binCnt[b] : 0;
        sum += v[q];
    }
    s_part[tid] = sum;
    __syncthreads();
    for (int off = 1; off < 1024; off <<= 1) {
        int x = 0;
        if (tid >= off) x = s_part[tid - off];
        __syncthreads();
        s_part[tid] += x;
        __syncthreads();
    }
    int run = s_part[tid] - sum;                 // exclusive
    #pragma unroll
    for (int q = 0; q < 4; q++) {
        const int b = base + q;
        if (b < bins) { g_binOff[b] = run; g_binCur[b] = run; run += v[q]; }
    }
    if (tid == 0) g_binOff[bins] = n_edges;
}

// Privatized scatter with range reservation: count locally, reserve one
// contiguous range per (CTA, bin) via a single global atomic, then place
// edges through smem cursors. Within-bin order is arbitrary (irrelevant).
__global__ void __launch_bounds__(256)
scatter_priv_kernel(const int* __restrict__ dst, const int* __restrict__ rel,
                    int n, int bins)
{
    __shared__ int s_h[BINS_CAP];
    const int tid = threadIdx.x;
    for (int i = tid; i < bins; i += 256) s_h[i] = 0;
    __syncthreads();
    const int per = (n + SORT_CTAS - 1) / SORT_CTAS;
    const int b0  = blockIdx.x * per;
    const int b1  = min(n, b0 + per);

    // pass 1: local counts
    for (int i = b0 + tid; i < b1; i += 256)
        atomicAdd(&s_h[(dst[i] >> 7) * NUM_RELS + rel[i]], 1);
    __syncthreads();

    // pass 2: reserve global ranges; s_h[bin] becomes the CTA's cursor base
    for (int i = tid; i < bins; i += 256) {
        const int c = s_h[i];
        if (c) s_h[i] = atomicAdd(&g_binCur[i], c);
    }
    __syncthreads();

    // pass 3: place edges via smem cursors
    for (int i = b0 + tid; i < b1; i += 256) {
        const int key = (dst[i] >> 7) * NUM_RELS + rel[i];
        const int p   = atomicAdd(&s_h[key], 1);
        g_eidx[p] = i;
    }
}

// ════════════════ fused aggregate + GEMM kernel ═════════════════════════
__global__ void __launch_bounds__(512, 1)
fused_kernel(const float* __restrict__ feat,
             const float* __restrict__ ew,
             const int*   __restrict__ src,
             const int*   __restrict__ dst,
             float*       __restrict__ out,
             int n_nodes)
{
    extern __shared__ char smem[];
    const uint32_t sbase = smem_u32(smem);
    const int tid  = threadIdx.x;
    const int wid  = tid >> 5;
    const int lane = tid & 31;
    const int t    = blockIdx.x;

    int*   s_src  = (int*)  (smem + OFF_SSRC);
    float* s_wv   = (float*)(smem + OFF_SW);
    int*   s_dl   = (int*)  (smem + OFF_SDL);
    int*   s_osrc = (int*)  (smem + OFF_OSRC);
    float* s_ow   = (float*)(smem + OFF_OW);
    int*   s_hist = (int*)  (smem + OFF_HIST);
    int*   s_rs   = (int*)  (smem + OFF_RS);
    int*   s_cur  = (int*)  (smem + OFF_CUR);

    const int n_rem = min(128, n_nodes - t * 128);

    // warp tiling for MMA: 4x4 warps, each 32x32
    const int m_base = (wid >> 2) * 32;
    const int n_base = (wid & 3) * 32;

    float accC[2][4][4];
    #pragma unroll
    for (int mt = 0; mt < 2; mt++)
        #pragma unroll
        for (int nt = 0; nt < 4; nt++)
            #pragma unroll
            for (int q = 0; q < 4; q++) accC[mt][nt][q] = 0.f;

    const uint32_t a_lane = (uint32_t)((lane & 15) * ROWB + (lane >> 4) * 16);
    const uint32_t b_lane = (uint32_t)((lane & 15) * ROWB + ((lane >> 4) & 1) * 16);

    for (int r = 0; r < NUM_RELS; r++) {
        const int key = t * NUM_RELS + r;
        const int bs  = g_binOff[key];
        const int be  = g_binOff[key + 1];

        float4 acc[8];
        #pragma unroll
        for (int q = 0; q < 8; q++) acc[q] = make_float4(0.f, 0.f, 0.f, 0.f);

        __syncthreads();   // previous rel's MMA done before smem reuse

        // W_r -> smem hoisted here: LDG latency overlaps the sort/aggregate
        // phase (OFF_W only read by the previous rel's MMA, ordered above).
        {
            const uint4* wg = (const uint4*)&g_Wh[r][0];
            #pragma unroll
            for (int i = tid; i < 2048; i += 512) {
                const int row = i >> 4, c16 = i & 15;
                *(uint4*)(smem + OFF_W + row * ROWB + c16 * 16) = wg[i];
            }
        }

        for (int c0 = bs; c0 < be; c0 += CAP) {
            const int c = min(CAP, be - c0);

            // stage edges
            for (int i = tid; i < c; i += 512) {
                const int e = g_eidx[c0 + i];
                s_src[i] = src[e];
                s_wv[i]  = ew[e];
                s_dl[i]  = dst[e] & 127;
            }
            if (tid < 128) s_hist[tid] = 0;
            __syncthreads();

            for (int i = tid; i < c; i += 512)
                atomicAdd(&s_hist[s_dl[i]], 1);
            __syncthreads();

            // warp 0: exclusive scan of 128 bins
            if (wid == 0) {
                const int b0 = lane * 4;
                const int v0 = s_hist[b0], v1 = s_hist[b0 + 1],
                          v2 = s_hist[b0 + 2], v3 = s_hist[b0 + 3];
                const int s = v0 + v1 + v2 + v3;
                int x = s;
                #pragma unroll
                for (int off = 1; off < 32; off <<= 1) {
                    const int y = __shfl_up_sync(0xFFFFFFFFu, x, off);
                    if (lane >= off) x += y;
                }
                const int excl = x - s;
                s_rs[b0]     = excl;            s_cur[b0]     = excl;
                s_rs[b0 + 1] = excl + v0;       s_cur[b0 + 1] = excl + v0;
                s_rs[b0 + 2] = excl + v0 + v1;  s_cur[b0 + 2] = excl + v0 + v1;
                s_rs[b0 + 3] = excl + v0 + v1 + v2;
                s_cur[b0 + 3] = s_rs[b0 + 3];
                if (lane == 31) s_rs[128] = excl + s;
            }
            __syncthreads();

            // scatter into dst-ordered arrays
            for (int i = tid; i < c; i += 512) {
                const int p = atomicAdd(&s_cur[s_dl[i]], 1);
                s_osrc[p] = s_src[i];
                s_ow[p]   = s_wv[i];
            }
            __syncthreads();

            // aggregation: warp w owns rows [8w, 8w+8)
            #pragma unroll
            for (int rr = 0; rr < 8; rr++) {
                int       j  = s_rs[8 * wid + rr];
                const int je = s_rs[8 * wid + rr + 1];
                for (; j + 1 < je; j += 2) {
                    const int   si0 = s_osrc[j],     si1 = s_osrc[j + 1];
                    const float w0  = s_ow[j],       w1  = s_ow[j + 1];
                    const float4 v0 = *(const float4*)(feat + (size_t)si0 * DIM + lane * 4);
                    const float4 v1 = *(const float4*)(feat + (size_t)si1 * DIM + lane * 4);
                    acc[rr].x += w0 * v0.x; acc[rr].y += w0 * v0.y;
                    acc[rr].z += w0 * v0.z; acc[rr].w += w0 * v0.w;
                    acc[rr].x += w1 * v1.x; acc[rr].y += w1 * v1.y;
                    acc[rr].z += w1 * v1.z; acc[rr].w += w1 * v1.w;
                }
                if (j < je) {
                    const int   si = s_osrc[j];
                    const float w  = s_ow[j];
                    const float4 v = *(const float4*)(feat + (size_t)si * DIM + lane * 4);
                    acc[rr].x += w * v.x; acc[rr].y += w * v.y;
                    acc[rr].z += w * v.z; acc[rr].w += w * v.w;
                }
            }
            __syncthreads();   // staging reused next chunk
        }

        // write A tile (fp16)
        #pragma unroll
        for (int rr = 0; rr < 8; rr++) {
            const int row = 8 * wid + rr;
            __half2 h0, h1;
            h0.x = __float2half(acc[rr].x); h0.y = __float2half(acc[rr].y);
            h1.x = __float2half(acc[rr].z); h1.y = __float2half(acc[rr].w);
            uint2 pk;
            pk.x = *(uint32_t*)&h0; pk.y = *(uint32_t*)&h1;
            *(uint2*)(smem + OFF_A + row * ROWB + lane * 8) = pk;
        }
        __syncthreads();

        // MMA: 8 k16-steps, single fp16 chain
        #pragma unroll
        for (int ks = 0; ks < 8; ks++) {
            uint32_t afr[2][4];
            #pragma unroll
            for (int mt = 0; mt < 2; mt++)
                ldsm_x4(afr[mt], sbase + OFF_A + (uint32_t)((m_base + mt * 16) * ROWB)
                                 + a_lane + (uint32_t)(ks * 32));
            uint32_t bfr[2][4];
            #pragma unroll
            for (int p = 0; p < 2; p++)
                ldsm_x4_t(bfr[p], sbase + OFF_W + (uint32_t)(ks * 16 * ROWB) + b_lane
                                     + (uint32_t)((n_base + p * 16) * 2));
            #pragma unroll
            for (int mt = 0; mt < 2; mt++)
                #pragma unroll
                for (int p = 0; p < 2; p++) {
                    mma16816(accC[mt][2 * p + 0], afr[mt], &bfr[p][0]);
                    mma16816(accC[mt][2 * p + 1], afr[mt], &bfr[p][2]);
                }
        }
    }
    __syncthreads();   // MMA done; A/W regions reusable as C staging

    // stage C then coalesced guarded stores — no atomics
    {
        float* Cst = (float*)smem;
        const int grp = lane >> 2;
        const int tig = lane & 3;
        #pragma unroll
        for (int mt = 0; mt < 2; mt++) {
            const int r0 = m_base + mt * 16 + grp;
            #pragma unroll
            for (int nt = 0; nt < 4; nt++) {
                const int col = n_base + nt * 8 + tig * 2;
                *(float2*)&Cst[r0 * CSTRIDE + col]       = make_float2(accC[mt][nt][0], accC[mt][nt][1]);
                *(float2*)&Cst[(r0 + 8) * CSTRIDE + col] = make_float2(accC[mt][nt][2], accC[mt][nt][3]);
            }
        }
    }
    __syncthreads();
    {
        const float* Cst = (const float*)smem;
        const int row = tid >> 2;          // 0..127
        const int seg = tid & 3;           // 32-float segment
        if (row < n_rem) {
            float4* op = (float4*)(out + (size_t)(t * 128 + row) * DIM + seg * 32);
            const float* cp = &Cst[row * CSTRIDE + seg * 32];
            #pragma unroll
            for (int j = 0; j < 8; j++)
                op[j] = *(const float4*)(cp + j * 4);
        }
    }
}

// ════════════════ launch ════════════════════════════════════════════════
extern "C" void kernel_launch(void* const* d_in, const int* in_sizes, int n_in,
                              void* d_out, int out_size)
{
    const float* feat    = (const float*)d_in[0];
    const float* rel_emb = (const float*)d_in[1];
    const float* ew      = (const float*)d_in[2];
    const int*   src     = (const int*)d_in[3];
    const int*   dst     = (const int*)d_in[4];
    const int*   rel     = (const int*)d_in[5];
    float*       out     = (float*)d_out;

    const int n_edges = in_sizes[2];
    const int n_nodes = in_sizes[0] / DIM;
    const int tiles   = (n_nodes + 127) / 128;
    const int bins    = tiles * NUM_RELS;

    static void* binCnt_ptr = nullptr;
    static int attr_set = 0;
    if (!attr_set) {
        cudaGetSymbolAddress(&binCnt_ptr, g_binCnt);
        cudaFuncSetAttribute(fused_kernel,
                             cudaFuncAttributeMaxDynamicSharedMemorySize, SMEM_F);
        attr_set = 1;
    }

    cudaMemsetAsync(binCnt_ptr, 0, (size_t)bins * sizeof(int), 0);
    repack_w_kernel<<<64, 256>>>(rel_emb);
    hist_priv_kernel<<<SORT_CTAS, 256>>>(dst, rel, n_edges, bins);
    scan_kernel<<<1, 1024>>>(bins, n_edges);
    scatter_priv_kernel<<<SORT_CTAS, 256>>>(dst, rel, n_edges, bins);
    fused_kernel<<<tiles, 512, SMEM_F>>>(feat, ew, src, dst, out, n_nodes);
}